// round 3
// baseline (speedup 1.0000x reference)
#include <cuda_runtime.h>
#include <math.h>

#define BB 2
#define TT 2048
#define SS 2048
#define DM 1024
#define NH 16
#define DH 64
#define KK 1024

// Scratch (static device globals — allocation-free rule)
__device__ float g_qn[(size_t)BB*NH*TT*DH];    // normalized+scaled Q, head layout
__device__ float g_kn[(size_t)BB*NH*SS*DH];    // normalized K, head layout
__device__ float g_vh[(size_t)BB*NH*SS*DH];    // projected V, head layout
__device__ float g_vals[(size_t)BB*TT*DM];     // attention output, [B,T,D]
__device__ float g_biasT[(size_t)NH*TT*SS];    // bias transposed to [H,T,S]

// ---------------------------------------------------------------------------
// Bias transpose: [T,S,H] -> [H,T,S]. Tile: 4 t x 64 s x 16 h. Coalesced both ways.
// ---------------------------------------------------------------------------
__global__ __launch_bounds__(256) void bias_transpose_kernel(const float* __restrict__ in) {
    __shared__ float sm[16 * 261];
    const int t0 = blockIdx.x * 4;
    const int s0 = blockIdx.y * 64;
    const int tid = threadIdx.x;
#pragma unroll
    for (int tt = 0; tt < 4; tt++) {
        const float* src = in + ((size_t)(t0 + tt) * SS + s0) * NH;
#pragma unroll
        for (int p = 0; p < 4; p++) {
            int idx = p * 256 + tid;       // 0..1023 over (ss, h)
            int h = idx & 15, ss = idx >> 4;
            sm[h * 261 + tt * 64 + ss] = src[idx];
        }
    }
    __syncthreads();
#pragma unroll
    for (int p = 0; p < 16; p++) {
        int idx = p * 256 + tid;           // 0..4095
        int ss = idx & 63;
        int combo = idx >> 6;              // (h, tt)
        int tt = combo & 3, h = combo >> 2;
        g_biasT[(size_t)h * TT * SS + (size_t)(t0 + tt) * SS + s0 + ss] =
            sm[h * 261 + tt * 64 + ss];
    }
}

// ---------------------------------------------------------------------------
// GEMM C = A[4096,1024] * W[1024,1024]^T   (NT: both K-contiguous)
// 64x64 tile, BK=16, 256 threads, 4x4 microtile.
// MODE 0: plain output (A = g_vals, C = d_out)
// MODE 1: head-layout output -> g_vh (V projection, no norm)
// MODE 2: head-layout + L2 row norm -> g_kn (K)
// MODE 3: head-layout + L2 norm + per-head logit scale -> g_qn (Q)
// ---------------------------------------------------------------------------
template <int MODE>
__global__ __launch_bounds__(256) void gemm_nt_kernel(const float* __restrict__ A,
                                                      const float* __restrict__ W,
                                                      float* __restrict__ Cplain,
                                                      const float* __restrict__ ls) {
    __shared__ float As[16][65];
    __shared__ float Ws[16][65];
    const int m0 = blockIdx.x * 64;
    const int n0 = blockIdx.y * 64;
    const int tid = threadIdx.x;
    const int tx = tid & 15, ty = tid >> 4;

    const float* Ar = (MODE == 0) ? (const float*)g_vals : A;

    float acc[4][4] = {};
    for (int k0 = 0; k0 < KK; k0 += 16) {
        int kk = tid & 15;
        int rbase = tid >> 4;
#pragma unroll
        for (int p = 0; p < 4; p++) {
            int r = p * 16 + rbase;
            As[kk][r] = Ar[(size_t)(m0 + r) * KK + k0 + kk];
            Ws[kk][r] = W[(size_t)(n0 + r) * KK + k0 + kk];
        }
        __syncthreads();
#pragma unroll
        for (int k = 0; k < 16; k++) {
            float a[4], b[4];
#pragma unroll
            for (int i = 0; i < 4; i++) a[i] = As[k][ty * 4 + i];
#pragma unroll
            for (int j = 0; j < 4; j++) b[j] = Ws[k][tx * 4 + j];
#pragma unroll
            for (int i = 0; i < 4; i++)
#pragma unroll
                for (int j = 0; j < 4; j++) acc[i][j] += a[i] * b[j];
        }
        __syncthreads();
    }

    if (MODE >= 2) {
        // L2-normalize each row over the 64 cols of this tile (== one head width)
        float inv[4];
#pragma unroll
        for (int i = 0; i < 4; i++) {
            float ssq = 0.f;
#pragma unroll
            for (int j = 0; j < 4; j++) ssq += acc[i][j] * acc[i][j];
#pragma unroll
            for (int msk = 8; msk; msk >>= 1)
                ssq += __shfl_xor_sync(0xffffffffu, ssq, msk, 16);
            inv[i] = 1.0f / fmaxf(sqrtf(ssq), 1e-12f);
        }
        float hscale = 1.0f;
        if (MODE == 3) {
            int h = n0 >> 6;
            hscale = expf(fminf(ls[h], 4.6051701859880914f)); // log(100)
        }
#pragma unroll
        for (int i = 0; i < 4; i++)
#pragma unroll
            for (int j = 0; j < 4; j++) acc[i][j] *= inv[i] * hscale;
    }

    float* Cp;
    if (MODE == 0) Cp = Cplain;
    else if (MODE == 1) Cp = g_vh;
    else if (MODE == 2) Cp = g_kn;
    else Cp = g_qn;

#pragma unroll
    for (int i = 0; i < 4; i++) {
        int m = m0 + ty * 4 + i;
#pragma unroll
        for (int j = 0; j < 4; j++) {
            int n = n0 + tx * 4 + j;
            if (MODE == 0) {
                Cp[(size_t)m * DM + n] = acc[i][j];
            } else {
                int b = m >> 11, t = m & 2047;
                int h = n >> 6, dh = n & 63;
                Cp[(((size_t)(b * NH + h)) * TT + t) * DH + dh] = acc[i][j];
            }
        }
    }
}

// ---------------------------------------------------------------------------
// Flash attention: per (b, h, 64-row q tile). Online softmax, fp32.
// Dynamic smem: Qs/Ks/Vs/Ps each 64x65 floats.
// ---------------------------------------------------------------------------
#define ATT_SMEM (4 * 64 * 65 * (int)sizeof(float))

__global__ __launch_bounds__(256) void attention_kernel() {
    extern __shared__ float sm[];
    float* Qs = sm;                 // [64][65]
    float* Ks = sm + 64 * 65;       // [64][65]
    float* Vs = sm + 2 * 64 * 65;   // [64][65]
    float* Ps = sm + 3 * 64 * 65;   // [64][65]

    const int t0 = blockIdx.x * 64;
    const int h = blockIdx.y;
    const int b = blockIdx.z;
    const int tid = threadIdx.x;
    const int tx = tid & 15, ty = tid >> 4;

    const float* qptr = g_qn + (((size_t)(b * NH + h)) * TT + t0) * DH;
    const float* kbase = g_kn + ((size_t)(b * NH + h)) * SS * DH;
    const float* vbase = g_vh + ((size_t)(b * NH + h)) * SS * DH;
    const float* bptr = g_biasT + (size_t)h * TT * SS + (size_t)t0 * SS;

    // Load Q tile once
#pragma unroll
    for (int p = 0; p < 16; p++) {
        int idx = p * 256 + tid;
        int r = idx >> 6, c = idx & 63;
        Qs[r * 65 + c] = qptr[(size_t)r * DH + c];
    }

    float m_prev[4], lsum[4], o[4][4];
#pragma unroll
    for (int i = 0; i < 4; i++) {
        m_prev[i] = -1e30f;
        lsum[i] = 0.f;
#pragma unroll
        for (int j = 0; j < 4; j++) o[i][j] = 0.f;
    }

    for (int s0 = 0; s0 < SS; s0 += 64) {
        __syncthreads();  // protect Ks/Vs/Ps from previous iteration reads
#pragma unroll
        for (int p = 0; p < 16; p++) {
            int idx = p * 256 + tid;
            int r = idx >> 6, c = idx & 63;
            Ks[r * 65 + c] = kbase[(size_t)(s0 + r) * DH + c];
            Vs[r * 65 + c] = vbase[(size_t)(s0 + r) * DH + c];
        }
        __syncthreads();

        // scores = Q * K^T
        float sc[4][4] = {};
#pragma unroll
        for (int k = 0; k < 64; k++) {
            float a[4], bv[4];
#pragma unroll
            for (int i = 0; i < 4; i++) a[i] = Qs[(ty * 4 + i) * 65 + k];
#pragma unroll
            for (int j = 0; j < 4; j++) bv[j] = Ks[(tx * 4 + j) * 65 + k];
#pragma unroll
            for (int i = 0; i < 4; i++)
#pragma unroll
                for (int j = 0; j < 4; j++) sc[i][j] += a[i] * bv[j];
        }
        // + bias (coalesced from transposed buffer)
#pragma unroll
        for (int i = 0; i < 4; i++) {
            const float* bp = bptr + (size_t)(ty * 4 + i) * SS + s0 + tx * 4;
#pragma unroll
            for (int j = 0; j < 4; j++) sc[i][j] += bp[j];
        }

        // online softmax (row reductions across the 16-lane tx group)
#pragma unroll
        for (int i = 0; i < 4; i++) {
            float mx = fmaxf(fmaxf(sc[i][0], sc[i][1]), fmaxf(sc[i][2], sc[i][3]));
#pragma unroll
            for (int msk = 8; msk; msk >>= 1)
                mx = fmaxf(mx, __shfl_xor_sync(0xffffffffu, mx, msk, 16));
            float m_new = fmaxf(m_prev[i], mx);
            float rs = 0.f;
#pragma unroll
            for (int j = 0; j < 4; j++) {
                sc[i][j] = __expf(sc[i][j] - m_new);
                rs += sc[i][j];
            }
#pragma unroll
            for (int msk = 8; msk; msk >>= 1)
                rs += __shfl_xor_sync(0xffffffffu, rs, msk, 16);
            float alpha = __expf(m_prev[i] - m_new);
            lsum[i] = lsum[i] * alpha + rs;
            m_prev[i] = m_new;
#pragma unroll
            for (int j = 0; j < 4; j++) o[i][j] *= alpha;
        }

        // stage P and do o += P * V
#pragma unroll
        for (int i = 0; i < 4; i++)
#pragma unroll
            for (int j = 0; j < 4; j++) Ps[(ty * 4 + i) * 65 + tx * 4 + j] = sc[i][j];
        __syncthreads();
#pragma unroll
        for (int k = 0; k < 64; k++) {
            float a[4], bv[4];
#pragma unroll
            for (int i = 0; i < 4; i++) a[i] = Ps[(ty * 4 + i) * 65 + k];
#pragma unroll
            for (int j = 0; j < 4; j++) bv[j] = Vs[k * 65 + tx * 4 + j];
#pragma unroll
            for (int i = 0; i < 4; i++)
#pragma unroll
                for (int j = 0; j < 4; j++) o[i][j] += a[i] * bv[j];
        }
    }

    // epilogue: divide by l, write to [B,T,D] for the output GEMM
#pragma unroll
    for (int i = 0; i < 4; i++) {
        float inv = 1.0f / lsum[i];
        int t = t0 + ty * 4 + i;
        float* dst = g_vals + ((size_t)(b * TT + t)) * DM + h * DH + tx * 4;
#pragma unroll
        for (int j = 0; j < 4; j++) dst[j] = o[i][j] * inv;
    }
}

// ---------------------------------------------------------------------------
extern "C" void kernel_launch(void* const* d_in, const int* in_sizes, int n_in,
                              void* d_out, int out_size) {
    const float* q    = (const float*)d_in[0];
    const float* k    = (const float*)d_in[1];
    const float* v    = (const float*)d_in[2];
    const float* bias = (const float*)d_in[3];
    const float* Wqkv = (const float*)d_in[4];
    const float* Wout = (const float*)d_in[5];
    const float* ls   = (const float*)d_in[6];
    float* out = (float*)d_out;

    cudaFuncSetAttribute(attention_kernel,
                         cudaFuncAttributeMaxDynamicSharedMemorySize, ATT_SMEM);

    bias_transpose_kernel<<<dim3(TT / 4, SS / 64), 256>>>(bias);

    dim3 ggrid(4096 / 64, DM / 64);
    gemm_nt_kernel<3><<<ggrid, 256>>>(q, Wqkv, nullptr, ls);       // Q: norm+scale
    gemm_nt_kernel<2><<<ggrid, 256>>>(k, Wqkv, nullptr, nullptr);  // K: norm
    gemm_nt_kernel<1><<<ggrid, 256>>>(v, Wqkv, nullptr, nullptr);  // V

    attention_kernel<<<dim3(TT / 64, NH, BB), 256, ATT_SMEM>>>();

    gemm_nt_kernel<0><<<ggrid, 256>>>(nullptr, Wout, out, nullptr); // output proj
}

// round 4
// speedup vs baseline: 1.5753x; 1.5753x over previous
#include <cuda_runtime.h>
#include <math.h>

#define BB 2
#define TT 2048
#define SS 2048
#define DM 1024
#define NH 16
#define DH 64
#define KK 1024

typedef unsigned long long ull;

// Scratch (static device globals — allocation-free rule)
__device__ float g_qn[(size_t)BB*NH*TT*DH];    // normalized+scaled Q  [b,h,t,d]
__device__ float g_kn[(size_t)BB*NH*SS*DH];    // normalized K         [b,h,s,d]
__device__ float g_vh[(size_t)BB*NH*SS*DH];    // projected V          [b,h,s,d]
__device__ float g_vals[(size_t)BB*TT*DM];     // attention output     [B,T,D]
__device__ float g_biasT[(size_t)NH*TT*SS];    // bias transposed to   [H,T,S]

// ---------------- f32x2 helpers (SASS FFMA2 path) ----------------
__device__ __forceinline__ void fma2(ull& d, ull a, ull b) {
    asm("fma.rn.f32x2 %0, %1, %2, %0;" : "+l"(d) : "l"(a), "l"(b));
}
__device__ __forceinline__ ull mul2(ull a, ull b) {
    ull d; asm("mul.rn.f32x2 %0, %1, %2;" : "=l"(d) : "l"(a), "l"(b)); return d;
}
__device__ __forceinline__ ull pk2(float x, float y) {
    ull r; asm("mov.b64 %0, {%1, %2};" : "=l"(r) : "f"(x), "f"(y)); return r;
}
__device__ __forceinline__ ull dup2(float x) { return pk2(x, x); }
__device__ __forceinline__ float2 u2(ull v) {
    float2 f; asm("mov.b64 {%0, %1}, %2;" : "=f"(f.x), "=f"(f.y) : "l"(v)); return f;
}

// ---------------------------------------------------------------------------
// Bias transpose: [T,S,H] -> [H,T,S]
// ---------------------------------------------------------------------------
__global__ __launch_bounds__(256) void bias_transpose_kernel(const float* __restrict__ in) {
    __shared__ float sm[16 * 261];
    const int t0 = blockIdx.x * 4;
    const int s0 = blockIdx.y * 64;
    const int tid = threadIdx.x;
#pragma unroll
    for (int tt = 0; tt < 4; tt++) {
        const float* src = in + ((size_t)(t0 + tt) * SS + s0) * NH;
#pragma unroll
        for (int p = 0; p < 4; p++) {
            int idx = p * 256 + tid;
            int h = idx & 15, ss = idx >> 4;
            sm[h * 261 + tt * 64 + ss] = src[idx];
        }
    }
    __syncthreads();
#pragma unroll
    for (int p = 0; p < 16; p++) {
        int idx = p * 256 + tid;
        int ss = idx & 63;
        int combo = idx >> 6;
        int tt = combo & 3, h = combo >> 2;
        g_biasT[(size_t)h * TT * SS + (size_t)(t0 + tt) * SS + s0 + ss] =
            sm[h * 261 + tt * 64 + ss];
    }
}

// ---------------------------------------------------------------------------
// GEMM C = A[4096,1024] * W[1024,1024]^T. 128x128 tile, BK=16, 256 thr, 8x8 micro.
// f32x2 accumulators (pairs along m). Double-buffered smem.
// W tile stored 16B-swizzled: cols n (0..127): phys = ((n&4)<<4) + ((n>>3)<<2) + (n&3)
// MODE 0: plain -> Cplain    MODE 1: head layout -> g_vh
// MODE 2: + L2 row norm -> g_kn     MODE 3: + norm + logit scale -> g_qn
// ---------------------------------------------------------------------------
template <int MODE>
__global__ __launch_bounds__(256) void gemm_nt_kernel(const float* __restrict__ A,
                                                      const float* __restrict__ W,
                                                      float* __restrict__ Cplain,
                                                      const float* __restrict__ ls) {
    __shared__ float As[2][16 * 132];
    __shared__ float Ws[2][16 * 132];
    const int m0 = blockIdx.x * 128;
    const int n0 = blockIdx.y * 128;
    const int tid = threadIdx.x;
    const int tx = tid & 15, ty = tid >> 4;

    const float* Ar = (MODE == 0) ? (const float*)g_vals : A;

    const int lm = tid >> 1;           // 0..127 row within tile
    const int lk = (tid & 1) * 8;      // 0 or 8
    const float* aP = Ar + (size_t)(m0 + lm) * KK + lk;
    const float* wP = W  + (size_t)(n0 + lm) * KK + lk;
    const int wphys = ((lm & 4) << 4) + ((lm >> 3) << 2) + (lm & 3); // swizzled col

    ull acc[4][8];
#pragma unroll
    for (int i = 0; i < 4; i++)
#pragma unroll
        for (int j = 0; j < 8; j++) acc[i][j] = 0ull;

    float4 ra[2], rw[2];
    ra[0] = *(const float4*)(aP);     ra[1] = *(const float4*)(aP + 4);
    rw[0] = *(const float4*)(wP);     rw[1] = *(const float4*)(wP + 4);

    int buf = 0;
    // store stage 0
    {
        const float* rav = (const float*)ra;
        const float* rwv = (const float*)rw;
#pragma unroll
        for (int e = 0; e < 8; e++) {
            As[0][(lk + e) * 132 + lm] = rav[e];
            Ws[0][(lk + e) * 132 + wphys] = rwv[e];
        }
    }
    __syncthreads();

    const int NK = KK / 16;
    for (int kt = 0; kt < NK; kt++) {
        if (kt + 1 < NK) {
            int ko = (kt + 1) * 16;
            ra[0] = *(const float4*)(aP + ko);  ra[1] = *(const float4*)(aP + ko + 4);
            rw[0] = *(const float4*)(wP + ko);  rw[1] = *(const float4*)(wP + ko + 4);
        }
#pragma unroll
        for (int k = 0; k < 16; k++) {
            const float* Ab = &As[buf][k * 132];
            const float* Wb = &Ws[buf][k * 132];
            ulonglong2 a0 = *(const ulonglong2*)(Ab + ty * 8);
            ulonglong2 a1 = *(const ulonglong2*)(Ab + ty * 8 + 4);
            float4 b0 = *(const float4*)(Wb + tx * 4);        // n = tx*8 .. +3
            float4 b1 = *(const float4*)(Wb + 64 + tx * 4);   // n = tx*8+4 .. +7
            float bj[8] = {b0.x, b0.y, b0.z, b0.w, b1.x, b1.y, b1.z, b1.w};
#pragma unroll
            for (int j = 0; j < 8; j++) {
                ull bd = dup2(bj[j]);
                fma2(acc[0][j], a0.x, bd);
                fma2(acc[1][j], a0.y, bd);
                fma2(acc[2][j], a1.x, bd);
                fma2(acc[3][j], a1.y, bd);
            }
        }
        if (kt + 1 < NK) {
            const float* rav = (const float*)ra;
            const float* rwv = (const float*)rw;
            int nb = buf ^ 1;
#pragma unroll
            for (int e = 0; e < 8; e++) {
                As[nb][(lk + e) * 132 + lm] = rav[e];
                Ws[nb][(lk + e) * 132 + wphys] = rwv[e];
            }
        }
        __syncthreads();
        buf ^= 1;
    }

    // unpack
    float cf[8][8];
#pragma unroll
    for (int i2 = 0; i2 < 4; i2++)
#pragma unroll
        for (int j = 0; j < 8; j++) {
            float2 f = u2(acc[i2][j]);
            cf[2 * i2][j] = f.x;
            cf[2 * i2 + 1][j] = f.y;
        }

    if (MODE >= 2) {
        float hscale = 1.0f;
        if (MODE == 3) {
            int h = blockIdx.y * 2 + (tx >> 3);
            hscale = expf(fminf(ls[h], 4.6051701859880914f));
        }
#pragma unroll
        for (int i = 0; i < 8; i++) {
            float ssq = 0.f;
#pragma unroll
            for (int j = 0; j < 8; j++) ssq += cf[i][j] * cf[i][j];
            ssq += __shfl_xor_sync(0xffffffffu, ssq, 1);
            ssq += __shfl_xor_sync(0xffffffffu, ssq, 2);
            ssq += __shfl_xor_sync(0xffffffffu, ssq, 4);
            float inv = hscale / fmaxf(sqrtf(ssq), 1e-12f);
#pragma unroll
            for (int j = 0; j < 8; j++) cf[i][j] *= inv;
        }
    }

    float* Cp;
    if (MODE == 0) Cp = Cplain;
    else if (MODE == 1) Cp = g_vh;
    else if (MODE == 2) Cp = g_kn;
    else Cp = g_qn;

#pragma unroll
    for (int i = 0; i < 8; i++) {
        int m = m0 + ty * 8 + i;
        int nb = n0 + tx * 8;
        float4 lo = make_float4(cf[i][0], cf[i][1], cf[i][2], cf[i][3]);
        float4 hi = make_float4(cf[i][4], cf[i][5], cf[i][6], cf[i][7]);
        if (MODE == 0) {
            float* dst = Cp + (size_t)m * DM + nb;
            *(float4*)dst = lo;
            *(float4*)(dst + 4) = hi;
        } else {
            int b = m >> 11, t = m & 2047;
            int h = nb >> 6, dh = nb & 63;
            float* dst = Cp + (((size_t)(b * NH + h)) * TT + t) * DH + dh;
            *(float4*)dst = lo;
            *(float4*)(dst + 4) = hi;
        }
    }
}

// ---------------------------------------------------------------------------
// Flash attention: BM=128 (t), BN=64 (s), 256 threads, 8x4 micro, f32x2.
// Smem: Qt[64][132] (d-major, t contig), Kt[64][68], Vs[64][68], Ps[64][132].
// ---------------------------------------------------------------------------
#define ATT_FLOATS (64*132 + 64*68 + 64*68 + 64*132)
#define ATT_SMEM (ATT_FLOATS * (int)sizeof(float))

__global__ __launch_bounds__(256) void attention_kernel() {
    extern __shared__ float sm[];
    float* Qt = sm;                        // [64][132]
    float* Kt = sm + 64 * 132;             // [64][68]
    float* Vs = Kt + 64 * 68;              // [64][68]
    float* Ps = Vs + 64 * 68;              // [64][132]

    const int t0 = blockIdx.x * 128;
    const int h = blockIdx.y;
    const int b = blockIdx.z;
    const int tid = threadIdx.x;
    const int tx = tid & 15, ty = tid >> 4;

    const float* qptr  = g_qn + (((size_t)(b * NH + h)) * TT + t0) * DH;
    const float* kbase = g_kn + ((size_t)(b * NH + h)) * SS * DH;
    const float* vbase = g_vh + ((size_t)(b * NH + h)) * SS * DH;
    const float* bptr  = g_biasT + (size_t)h * TT * SS + (size_t)t0 * SS;

    // Load Q tile once, transposed: Qt[d][m]
    {
        int m = tid >> 1;
        int dc0 = (tid & 1) * 32;
        const float* qp = qptr + (size_t)m * DH + dc0;
#pragma unroll
        for (int q = 0; q < 8; q++) {
            float4 v = *(const float4*)(qp + q * 4);
            int d = dc0 + q * 4;
            Qt[(d + 0) * 132 + m] = v.x;
            Qt[(d + 1) * 132 + m] = v.y;
            Qt[(d + 2) * 132 + m] = v.z;
            Qt[(d + 3) * 132 + m] = v.w;
        }
    }

    float m_prev[8], lsum[8];
    ull o2[4][4];
#pragma unroll
    for (int i = 0; i < 8; i++) { m_prev[i] = -1e30f; lsum[i] = 0.f; }
#pragma unroll
    for (int i2 = 0; i2 < 4; i2++)
#pragma unroll
        for (int j = 0; j < 4; j++) o2[i2][j] = 0ull;

    for (int s0 = 0; s0 < SS; s0 += 64) {
        __syncthreads();
        // load K (transposed) and V tiles
        {
            int s = tid >> 2;
            int dc = (tid & 3) * 16;
            const float* kp = kbase + (size_t)(s0 + s) * DH + dc;
            const float* vp = vbase + (size_t)(s0 + s) * DH + dc;
#pragma unroll
            for (int q = 0; q < 4; q++) {
                float4 kv = *(const float4*)(kp + q * 4);
                int d = dc + q * 4;
                Kt[(d + 0) * 68 + s] = kv.x;
                Kt[(d + 1) * 68 + s] = kv.y;
                Kt[(d + 2) * 68 + s] = kv.z;
                Kt[(d + 3) * 68 + s] = kv.w;
            }
#pragma unroll
            for (int q = 0; q < 4; q++) {
                float4 vv = *(const float4*)(vp + q * 4);
                *(float4*)&Vs[s * 68 + dc + q * 4] = vv;
            }
        }
        __syncthreads();

        // S = Q K^T  (f32x2, pairs along m)
        ull acc2[4][4];
#pragma unroll
        for (int i2 = 0; i2 < 4; i2++)
#pragma unroll
            for (int j = 0; j < 4; j++) acc2[i2][j] = 0ull;
#pragma unroll 8
        for (int d = 0; d < 64; d++) {
            ulonglong2 a0 = *(const ulonglong2*)&Qt[d * 132 + ty * 8];
            ulonglong2 a1 = *(const ulonglong2*)&Qt[d * 132 + ty * 8 + 4];
            float4 bv = *(const float4*)&Kt[d * 68 + tx * 4];
            float bj[4] = {bv.x, bv.y, bv.z, bv.w};
#pragma unroll
            for (int j = 0; j < 4; j++) {
                ull bd = dup2(bj[j]);
                fma2(acc2[0][j], a0.x, bd);
                fma2(acc2[1][j], a0.y, bd);
                fma2(acc2[2][j], a1.x, bd);
                fma2(acc2[3][j], a1.y, bd);
            }
        }

        // unpack, add bias
        float sc[8][4];
#pragma unroll
        for (int i2 = 0; i2 < 4; i2++)
#pragma unroll
            for (int j = 0; j < 4; j++) {
                float2 f = u2(acc2[i2][j]);
                sc[2 * i2][j] = f.x;
                sc[2 * i2 + 1][j] = f.y;
            }
#pragma unroll
        for (int i = 0; i < 8; i++) {
            float4 bb = *(const float4*)(bptr + (size_t)(ty * 8 + i) * SS + s0 + tx * 4);
            sc[i][0] += bb.x; sc[i][1] += bb.y; sc[i][2] += bb.z; sc[i][3] += bb.w;
        }

        // online softmax
        float alpha[8];
#pragma unroll
        for (int i = 0; i < 8; i++) {
            float mx = fmaxf(fmaxf(sc[i][0], sc[i][1]), fmaxf(sc[i][2], sc[i][3]));
            mx = fmaxf(mx, __shfl_xor_sync(0xffffffffu, mx, 1));
            mx = fmaxf(mx, __shfl_xor_sync(0xffffffffu, mx, 2));
            mx = fmaxf(mx, __shfl_xor_sync(0xffffffffu, mx, 4));
            mx = fmaxf(mx, __shfl_xor_sync(0xffffffffu, mx, 8));
            float m_new = fmaxf(m_prev[i], mx);
            float rs = 0.f;
#pragma unroll
            for (int j = 0; j < 4; j++) {
                sc[i][j] = __expf(sc[i][j] - m_new);
                rs += sc[i][j];
            }
            rs += __shfl_xor_sync(0xffffffffu, rs, 1);
            rs += __shfl_xor_sync(0xffffffffu, rs, 2);
            rs += __shfl_xor_sync(0xffffffffu, rs, 4);
            rs += __shfl_xor_sync(0xffffffffu, rs, 8);
            alpha[i] = __expf(m_prev[i] - m_new);
            lsum[i] = lsum[i] * alpha[i] + rs;
            m_prev[i] = m_new;
        }
#pragma unroll
        for (int i2 = 0; i2 < 4; i2++) {
            ull al = pk2(alpha[2 * i2], alpha[2 * i2 + 1]);
#pragma unroll
            for (int j = 0; j < 4; j++) o2[i2][j] = mul2(o2[i2][j], al);
        }

        // stage P transposed: Ps[s][m]
#pragma unroll
        for (int j = 0; j < 4; j++) {
            int sr = (tx * 4 + j) * 132 + ty * 8;
            *(float4*)&Ps[sr]     = make_float4(sc[0][j], sc[1][j], sc[2][j], sc[3][j]);
            *(float4*)&Ps[sr + 4] = make_float4(sc[4][j], sc[5][j], sc[6][j], sc[7][j]);
        }
        __syncthreads();

        // O += P V
#pragma unroll 8
        for (int s = 0; s < 64; s++) {
            ulonglong2 a0 = *(const ulonglong2*)&Ps[s * 132 + ty * 8];
            ulonglong2 a1 = *(const ulonglong2*)&Ps[s * 132 + ty * 8 + 4];
            float4 bv = *(const float4*)&Vs[s * 68 + tx * 4];
            float bj[4] = {bv.x, bv.y, bv.z, bv.w};
#pragma unroll
            for (int j = 0; j < 4; j++) {
                ull bd = dup2(bj[j]);
                fma2(o2[0][j], a0.x, bd);
                fma2(o2[1][j], a0.y, bd);
                fma2(o2[2][j], a1.x, bd);
                fma2(o2[3][j], a1.y, bd);
            }
        }
    }

    // epilogue
    float ov[8][4];
#pragma unroll
    for (int i2 = 0; i2 < 4; i2++) {
        float inv0 = 1.0f / lsum[2 * i2];
        float inv1 = 1.0f / lsum[2 * i2 + 1];
#pragma unroll
        for (int j = 0; j < 4; j++) {
            float2 f = u2(o2[i2][j]);
            ov[2 * i2][j] = f.x * inv0;
            ov[2 * i2 + 1][j] = f.y * inv1;
        }
    }
#pragma unroll
    for (int i = 0; i < 8; i++) {
        int t = t0 + ty * 8 + i;
        float* dst = g_vals + ((size_t)(b * TT + t)) * DM + h * DH + tx * 4;
        *(float4*)dst = make_float4(ov[i][0], ov[i][1], ov[i][2], ov[i][3]);
    }
}

// ---------------------------------------------------------------------------
extern "C" void kernel_launch(void* const* d_in, const int* in_sizes, int n_in,
                              void* d_out, int out_size) {
    const float* q    = (const float*)d_in[0];
    const float* k    = (const float*)d_in[1];
    const float* v    = (const float*)d_in[2];
    const float* bias = (const float*)d_in[3];
    const float* Wqkv = (const float*)d_in[4];
    const float* Wout = (const float*)d_in[5];
    const float* ls   = (const float*)d_in[6];
    float* out = (float*)d_out;

    cudaFuncSetAttribute(attention_kernel,
                         cudaFuncAttributeMaxDynamicSharedMemorySize, ATT_SMEM);

    bias_transpose_kernel<<<dim3(TT / 4, SS / 64), 256>>>(bias);

    dim3 ggrid(4096 / 128, DM / 128);   // (32, 8)
    gemm_nt_kernel<3><<<ggrid, 256>>>(q, Wqkv, nullptr, ls);       // Q: norm+scale
    gemm_nt_kernel<2><<<ggrid, 256>>>(k, Wqkv, nullptr, nullptr);  // K: norm
    gemm_nt_kernel<1><<<ggrid, 256>>>(v, Wqkv, nullptr, nullptr);  // V

    attention_kernel<<<dim3(TT / 128, NH, BB), 256, ATT_SMEM>>>();

    gemm_nt_kernel<0><<<ggrid, 256>>>(nullptr, Wout, out, nullptr); // output proj
}